// round 14
// baseline (speedup 1.0000x reference)
#include <cuda_runtime.h>
#include <cuda_fp16.h>
#include <cstdint>

#define D 64
#define MAX_NODES 50000
#define CAP 128    // per-node bucket capacity; Poisson(20) max deg ~50
#define NTILE 128
#define MAX_TILES ((MAX_NODES + NTILE - 1) / NTILE)   // 391

// Scratch (no cudaMalloc allowed). g_cnt is zero-init at module load and
// re-zeroed by the gather kernel's tail each invocation.
__device__ int g_cnt[MAX_NODES];
__device__ int g_bucket[(size_t)MAX_NODES * CAP];                 // 25.6 MB
// A image: f16 row-major [node][128]: cols 0-63 = x (prep), 64-127 = agg
// (gather). The gather READS the x-half as its fp16 source mirror.
__device__ __align__(16) __half2 g_Ah[(size_t)MAX_TILES * NTILE * 64];  // 12.8 MB
// B image: f16 row-major [o][128] = [U | V] rows.
__device__ __align__(16) __half g_Bh[64 * 128];

__device__ __forceinline__ unsigned h2pack(float a, float b) {
    __half2 h = __floats2half2_rn(a, b);
    return *reinterpret_cast<unsigned*>(&h);
}

// ---------------------------------------------------------------------------
// Kernel 1: prep. Build f16 B image; convert x into the x-half of the A
// image. (No counter zeroing -> independent of the fill kernel.)
// ---------------------------------------------------------------------------
__global__ void prep_kernel(const float* __restrict__ U,
                            const float* __restrict__ V,
                            const float* __restrict__ x,
                            int nNodes) {
    int i = blockIdx.x * blockDim.x + threadIdx.x;
    if (i < 64 * 128) {
        int n = i >> 7, k = i & 127;
        float val = (k < 64) ? __ldg(U + n * 64 + k) : __ldg(V + n * 64 + (k - 64));
        g_Bh[n * 128 + k] = __float2half(val);
    }
    if (i < nNodes * 16) {
        int node = i >> 4, c = i & 15;     // one float4 per thread
        float4 v = __ldg(reinterpret_cast<const float4*>(x) + (size_t)node * 16 + c);
        uint2 p;
        p.x = h2pack(v.x, v.y);
        p.y = h2pack(v.z, v.w);
        *reinterpret_cast<uint2*>(&g_Ah[(size_t)node * 64 + 2 * c]) = p;
    }
}

// ---------------------------------------------------------------------------
// Kernel 2: bucket fill, 4 edges per thread via int4 loads.
// ---------------------------------------------------------------------------
__global__ void fill_buckets_kernel(const int* __restrict__ src,
                                    const int* __restrict__ dst,
                                    int nEdges) {
    int q = blockIdx.x * blockDim.x + threadIdx.x;
    int e0 = q << 2;
    if (e0 + 4 <= nEdges) {
        int4 s4 = __ldg(reinterpret_cast<const int4*>(src + e0));
        int4 d4 = __ldg(reinterpret_cast<const int4*>(dst + e0));
        int p0 = atomicAdd(&g_cnt[d4.x], 1);
        int p1 = atomicAdd(&g_cnt[d4.y], 1);
        int p2 = atomicAdd(&g_cnt[d4.z], 1);
        int p3 = atomicAdd(&g_cnt[d4.w], 1);
        if (p0 < CAP) g_bucket[(size_t)d4.x * CAP + p0] = s4.x;
        if (p1 < CAP) g_bucket[(size_t)d4.y * CAP + p1] = s4.y;
        if (p2 < CAP) g_bucket[(size_t)d4.z * CAP + p2] = s4.z;
        if (p3 < CAP) g_bucket[(size_t)d4.w * CAP + p3] = s4.w;
    } else {
        for (int e = e0; e < nEdges; e++) {
            int d = __ldg(dst + e);
            int s = __ldg(src + e);
            int pos = atomicAdd(&g_cnt[d], 1);
            if (pos < CAP) g_bucket[(size_t)d * CAP + pos] = s;
        }
    }
}

// ---------------------------------------------------------------------------
// Kernel 3: pull-gather over the fp16 x-image, FOUR nodes per warp (one per
// quarter-warp: 8 lanes x uint4 = 128B row). 4 independent chains per warp.
// fp32 accumulation; fp16 round once at the end. Tail re-zeroes g_cnt for
// the next graph replay.
// ---------------------------------------------------------------------------
__global__ __launch_bounds__(256) void gather_kernel(int nNodes) {
    int warp = (blockIdx.x * blockDim.x + threadIdx.x) >> 5;
    int lane = threadIdx.x & 31;
    int il = lane & 7;                       // lane within quarter-warp
    int node = (warp << 2) | (lane >> 3);    // quarter-warp's node
    if (node >= nNodes) return;

    int cnt = __ldg(g_cnt + node);
    if (il == 0) g_cnt[node] = 0;            // reset for next invocation
    cnt = cnt < CAP ? cnt : CAP;
    const int* row = g_bucket + (size_t)node * CAP;

    float acc[8];
    #pragma unroll
    for (int j = 0; j < 8; j++) acc[j] = 0.f;

    int e = 0;
    for (; e + 8 <= cnt; e += 8) {
        int s[8];
        #pragma unroll
        for (int k = 0; k < 8; k++) s[k] = __ldg(row + e + k);
        uint4 h[8];
        #pragma unroll
        for (int k = 0; k < 8; k++)
            h[k] = *reinterpret_cast<const uint4*>(&g_Ah[(size_t)s[k] * 64 + 4 * il]);
        #pragma unroll
        for (int k = 0; k < 8; k++) {
            float2 f0 = __half22float2(*reinterpret_cast<__half2*>(&h[k].x));
            float2 f1 = __half22float2(*reinterpret_cast<__half2*>(&h[k].y));
            float2 f2 = __half22float2(*reinterpret_cast<__half2*>(&h[k].z));
            float2 f3 = __half22float2(*reinterpret_cast<__half2*>(&h[k].w));
            acc[0] += f0.x; acc[1] += f0.y;
            acc[2] += f1.x; acc[3] += f1.y;
            acc[4] += f2.x; acc[5] += f2.y;
            acc[6] += f3.x; acc[7] += f3.y;
        }
    }
    for (; e < cnt; e++) {
        int s = __ldg(row + e);
        uint4 h = *reinterpret_cast<const uint4*>(&g_Ah[(size_t)s * 64 + 4 * il]);
        float2 f0 = __half22float2(*reinterpret_cast<__half2*>(&h.x));
        float2 f1 = __half22float2(*reinterpret_cast<__half2*>(&h.y));
        float2 f2 = __half22float2(*reinterpret_cast<__half2*>(&h.z));
        float2 f3 = __half22float2(*reinterpret_cast<__half2*>(&h.w));
        acc[0] += f0.x; acc[1] += f0.y;
        acc[2] += f1.x; acc[3] += f1.y;
        acc[4] += f2.x; acc[5] += f2.y;
        acc[6] += f3.x; acc[7] += f3.y;
    }

    uint4 pa;
    pa.x = h2pack(acc[0], acc[1]);
    pa.y = h2pack(acc[2], acc[3]);
    pa.z = h2pack(acc[4], acc[5]);
    pa.w = h2pack(acc[6], acc[7]);
    *reinterpret_cast<uint4*>(&g_Ah[(size_t)node * 64 + 32 + 4 * il]) = pa;
}

// ---------------------------------------------------------------------------
// Kernel 4: HMMA GEMM + ReLU (unchanged; 10.6us measured).
// ---------------------------------------------------------------------------
#define AROW 136
#define MMA_SMEM_BYTES ((NTILE * AROW + 64 * AROW) * 2)   // 52224

__global__ __launch_bounds__(128) void mma_kernel(float* __restrict__ out,
                                                  int nNodes) {
    extern __shared__ __align__(16) unsigned char smem[];
    __half* As = reinterpret_cast<__half*>(smem);                 // 128 x 136
    __half* Bs = reinterpret_cast<__half*>(smem) + NTILE * AROW;  // 64 x 136
    uint32_t smem_u32;
    asm("{ .reg .u64 t; cvta.to.shared.u64 t, %1; cvt.u32.u64 %0, t; }"
        : "=r"(smem_u32) : "l"(smem));
    uint32_t sA = smem_u32;
    uint32_t sB = smem_u32 + NTILE * AROW * 2;

    int tid = threadIdx.x;
    int w = tid >> 5, l = tid & 31;
    int nodeBase = blockIdx.x * NTILE;

    {
        const float4* gA = reinterpret_cast<const float4*>(
            g_Ah + (size_t)blockIdx.x * NTILE * 64);
        #pragma unroll
        for (int k = 0; k < 16; k++) {
            int i4 = tid + k * 128;
            int r = i4 >> 4, c = i4 & 15;
            *reinterpret_cast<float4*>(As + r * AROW + c * 8) = gA[i4];
        }
        const float4* gB = reinterpret_cast<const float4*>(g_Bh);
        #pragma unroll
        for (int k = 0; k < 8; k++) {
            int i4 = tid + k * 128;
            int r = i4 >> 4, c = i4 & 15;
            *reinterpret_cast<float4*>(Bs + r * AROW + c * 8) = gB[i4];
        }
    }
    __syncthreads();

    int aRowInTile = (l & 7) | (l & 8);
    uint32_t aColOff = (uint32_t)(((l >> 4) & 1) * 16);
    uint32_t bAddrBase = sB + (uint32_t)((l & 7) * AROW * 2) +
                         (uint32_t)(((l >> 3) & 1) * 16);

    float acc[2][8][4];
    #pragma unroll
    for (int mt = 0; mt < 2; mt++)
        #pragma unroll
        for (int nt = 0; nt < 8; nt++)
            #pragma unroll
            for (int q = 0; q < 4; q++) acc[mt][nt][q] = 0.f;

    #pragma unroll
    for (int ks = 0; ks < 8; ks++) {
        uint32_t kByte = (uint32_t)(ks * 32);
        uint32_t bf[8][2];
        #pragma unroll
        for (int nt = 0; nt < 8; nt++) {
            uint32_t addr = bAddrBase + (uint32_t)(nt * 8 * AROW * 2) + kByte;
            asm volatile("ldmatrix.sync.aligned.m8n8.x2.shared.b16 {%0,%1}, [%2];"
                         : "=r"(bf[nt][0]), "=r"(bf[nt][1]) : "r"(addr));
        }
        #pragma unroll
        for (int mt = 0; mt < 2; mt++) {
            uint32_t a0, a1, a2, a3;
            uint32_t addr = sA +
                (uint32_t)((w * 32 + mt * 16 + aRowInTile) * AROW * 2) +
                kByte + aColOff;
            asm volatile("ldmatrix.sync.aligned.m8n8.x4.shared.b16 {%0,%1,%2,%3}, [%4];"
                         : "=r"(a0), "=r"(a1), "=r"(a2), "=r"(a3) : "r"(addr));
            #pragma unroll
            for (int nt = 0; nt < 8; nt++) {
                asm volatile(
                    "mma.sync.aligned.m16n8k16.row.col.f32.f16.f16.f32 "
                    "{%0,%1,%2,%3}, {%4,%5,%6,%7}, {%8,%9}, {%0,%1,%2,%3};"
                    : "+f"(acc[mt][nt][0]), "+f"(acc[mt][nt][1]),
                      "+f"(acc[mt][nt][2]), "+f"(acc[mt][nt][3])
                    : "r"(a0), "r"(a1), "r"(a2), "r"(a3),
                      "r"(bf[nt][0]), "r"(bf[nt][1]));
            }
        }
    }

    int q = l >> 2, qt = l & 3;
    #pragma unroll
    for (int mt = 0; mt < 2; mt++) {
        int r0 = nodeBase + w * 32 + mt * 16 + q;
        int r1 = r0 + 8;
        #pragma unroll
        for (int nt = 0; nt < 8; nt++) {
            int col = nt * 8 + qt * 2;
            if (r0 < nNodes) {
                float2 o0;
                o0.x = fmaxf(acc[mt][nt][0], 0.f);
                o0.y = fmaxf(acc[mt][nt][1], 0.f);
                *reinterpret_cast<float2*>(out + (size_t)r0 * D + col) = o0;
            }
            if (r1 < nNodes) {
                float2 o1;
                o1.x = fmaxf(acc[mt][nt][2], 0.f);
                o1.y = fmaxf(acc[mt][nt][3], 0.f);
                *reinterpret_cast<float2*>(out + (size_t)r1 * D + col) = o1;
            }
        }
    }
}

// ---------------------------------------------------------------------------
// Launch DAG:  [stream0] fill ──────┐
//              [stream2] prep ──────┴─> gather -> MMA   (fork/join via events)
// Streams/events created once on the first (uncaptured) correctness call.
// ---------------------------------------------------------------------------
extern "C" void kernel_launch(void* const* d_in, const int* in_sizes, int n_in,
                              void* d_out, int out_size) {
    const float* x   = (const float*)d_in[0];
    const int*   src = (const int*)d_in[1];
    const int*   dst = (const int*)d_in[2];
    const float* U   = (const float*)d_in[3];
    const float* V   = (const float*)d_in[4];
    float* out = (float*)d_out;

    int nNodes = in_sizes[0] / D;
    int nEdges = in_sizes[1];
    int nTiles = (nNodes + NTILE - 1) / NTILE;

    static cudaStream_t s2 = nullptr;
    static cudaEvent_t evFork = nullptr, evJoin = nullptr;
    if (!s2) {
        cudaStreamCreateWithFlags(&s2, cudaStreamNonBlocking);
        cudaEventCreateWithFlags(&evFork, cudaEventDisableTiming);
        cudaEventCreateWithFlags(&evJoin, cudaEventDisableTiming);
        cudaFuncSetAttribute(mma_kernel,
                             cudaFuncAttributeMaxDynamicSharedMemorySize,
                             MMA_SMEM_BYTES);
    }

    // Fork: prep on s2, fill on the main stream.
    cudaEventRecord(evFork, 0);
    cudaStreamWaitEvent(s2, evFork, 0);

    int prepN = nNodes * 16;
    prep_kernel<<<(prepN + 255) / 256, 256, 0, s2>>>(U, V, x, nNodes);
    cudaEventRecord(evJoin, s2);

    int fq = (nEdges + 3) / 4;
    fill_buckets_kernel<<<(fq + 255) / 256, 256>>>(src, dst, nEdges);

    // Join: gather needs buckets (stream 0) + x-image (s2).
    cudaStreamWaitEvent(0, evJoin, 0);

    int gwarps = (nNodes + 3) / 4;
    int gblocks = (gwarps * 32 + 255) / 256;
    gather_kernel<<<gblocks, 256>>>(nNodes);

    mma_kernel<<<nTiles, 128, MMA_SMEM_BYTES>>>(out, nNodes);
}